// round 14
// baseline (speedup 1.0000x reference)
#include <cuda_runtime.h>
#include <cuda_fp16.h>
#include <math_constants.h>
#include <cstdint>

#define TOKENS  8192
#define HIDDEN  6144
#define EXPERTS 768
#define TOPK    12
#define NCAND   13
#define RSCALE  2.5f
#define TAU     1e-4f

// ---------------- GEMM config ----------------
#define BM 128
#define BN 128
#define BK 64
#define NSTAGES (HIDDEN / BK)    // 96
#define RING 3
#define TILE_B  (BM * 128)
#define STAGE_B (2 * TILE_B)
#define GEMM_SMEM (RING * STAGE_B)  // 98304

#define NA4 (TOKENS * HIDDEN / 4)
#define NW4 (EXPERTS * HIDDEN / 4)
#define CVT_BLOCKS ((NA4 + NW4) / (256 * 4))   // 13440 exact

__device__ __half g_Ah[(size_t)TOKENS * HIDDEN];
__device__ __half g_Wh[(size_t)EXPERTS * HIDDEN];
__device__ float  g_logits[(size_t)TOKENS * EXPERTS];

// ---------------- helpers ----------------
__device__ __forceinline__ uint32_t smem_u32(const void* p) {
    uint32_t a;
    asm("{ .reg .u64 t; cvta.to.shared.u64 t, %1; cvt.u32.u64 %0, t; }" : "=r"(a) : "l"(p));
    return a;
}
__device__ __forceinline__ uint2 f4_to_h4(float4 v) {
    __half2 p0 = __floats2half2_rn(v.x, v.y);
    __half2 p1 = __floats2half2_rn(v.z, v.w);
    return make_uint2(*(uint32_t*)&p0, *(uint32_t*)&p1);
}
__device__ __forceinline__ void cp16(uint32_t dst, const void* src) {
    asm volatile("cp.async.cg.shared.global [%0], [%1], 16;" :: "r"(dst), "l"(src) : "memory");
}
#define CP_COMMIT() asm volatile("cp.async.commit_group;" ::: "memory")
#define CP_WAIT1()  asm volatile("cp.async.wait_group 1;" ::: "memory")

__device__ __forceinline__ void ldm_x4(uint32_t* r, uint32_t addr) {
    asm volatile("ldmatrix.sync.aligned.m8n8.x4.shared.b16 {%0,%1,%2,%3}, [%4];"
                 : "=r"(r[0]), "=r"(r[1]), "=r"(r[2]), "=r"(r[3]) : "r"(addr));
}
__device__ __forceinline__ void mma16(float* c, const uint32_t* a, const uint32_t* b) {
    asm volatile(
        "mma.sync.aligned.m16n8k16.row.col.f32.f16.f16.f32 "
        "{%0,%1,%2,%3}, {%4,%5,%6,%7}, {%8,%9}, {%0,%1,%2,%3};"
        : "+f"(c[0]), "+f"(c[1]), "+f"(c[2]), "+f"(c[3])
        : "r"(a[0]), "r"(a[1]), "r"(a[2]), "r"(a[3]), "r"(b[0]), "r"(b[1]));
}
__device__ __forceinline__ uint32_t swz(int row, int ch) {
    return (uint32_t)(row * 128 + ((ch ^ (row & 7)) << 4));
}
__device__ __forceinline__ uint32_t fkey(float x) {
    uint32_t u = __float_as_uint(x);
    return (u & 0x80000000u) ? ~u : (u | 0x80000000u);
}
__device__ __forceinline__ float fval(uint32_t k) {
    uint32_t u = (k & 0x80000000u) ? (k & 0x7FFFFFFFu) : ~k;
    return __uint_as_float(u);
}

// ---------------------------------------------------------------------------
// Merged fp32->fp16 conversion (R13, at DRAM floor).
// ---------------------------------------------------------------------------
__global__ __launch_bounds__(256)
void cvt_all_kernel(const float4* __restrict__ inA, const float4* __restrict__ inW,
                    uint2* __restrict__ outA, uint2* __restrict__ outW) {
    const int base   = blockIdx.x * blockDim.x + threadIdx.x;
    const int stride = gridDim.x * blockDim.x;
    #pragma unroll
    for (int k = 0; k < 4; k++) {
        const int i = base + k * stride;
        if (i < NA4) outA[i] = f4_to_h4(inA[i]);
        else         outW[i - NA4] = f4_to_h4(inW[i - NA4]);
    }
}

// ---------------------------------------------------------------------------
// fp16 GEMM, cp.async ring-3, SW128 smem, one sync/stage (R13).
// ---------------------------------------------------------------------------
__global__ __launch_bounds__(256, 2)
void router_gemm_cp() {
    extern __shared__ char smem[];
    const uint32_t smbase = smem_u32(smem);

    const int tid  = threadIdx.x;
    const int wid  = tid >> 5;
    const int lane = tid & 31;
    const int m0 = blockIdx.y * BM;
    const int n0 = blockIdx.x * BN;

    const int wm = wid & 1;
    const int wn = wid >> 1;
    const int wrow = tid >> 3;
    const int wc   = tid & 7;

    const __half* Abase = g_Ah + (size_t)m0 * HIDDEN;
    const __half* Bbase = g_Wh + (size_t)n0 * HIDDEN;

    float acc[4][4][4];
    #pragma unroll
    for (int mi = 0; mi < 4; mi++)
        #pragma unroll
        for (int ni = 0; ni < 4; ni++)
            #pragma unroll
            for (int j = 0; j < 4; j++) acc[mi][ni][j] = 0.0f;

    auto issue = [&](int s) {
        const uint32_t slot = smbase + (s % RING) * STAGE_B;
        const __half* ga = Abase + s * BK;
        const __half* gb = Bbase + s * BK;
        #pragma unroll
        for (int i = 0; i < 4; i++) {
            const int row = wrow + 32 * i;
            const uint32_t so = swz(row, wc);
            cp16(slot + so,          ga + (size_t)row * HIDDEN + wc * 8);
            cp16(slot + TILE_B + so, gb + (size_t)row * HIDDEN + wc * 8);
        }
    };

    issue(0); CP_COMMIT();
    issue(1); CP_COMMIT();

    const int a_row = wm * 64 + (lane & 7) + ((lane >> 3) & 1) * 8;
    const int a_chl = (lane >> 4) & 1;
    const int b_row = wn * 32 + (lane & 7) + ((lane >> 4) & 1) * 8;
    const int b_chl = (lane >> 3) & 1;

    for (int s = 0; s < NSTAGES; s++) {
        CP_WAIT1();
        __syncthreads();
        if (s + 2 < NSTAGES) issue(s + 2);
        CP_COMMIT();

        const uint32_t sA = smbase + (s % RING) * STAGE_B;
        const uint32_t sB = sA + TILE_B;

        #pragma unroll
        for (int w = 0; w < 4; w++) {
            uint32_t af[4][4], bf[2][4];
            #pragma unroll
            for (int mi = 0; mi < 4; mi++)
                ldm_x4(af[mi], sA + swz(a_row + mi * 16, w * 2 + a_chl));
            #pragma unroll
            for (int p = 0; p < 2; p++)
                ldm_x4(bf[p], sB + swz(b_row + p * 16, w * 2 + b_chl));
            #pragma unroll
            for (int mi = 0; mi < 4; mi++) {
                mma16(acc[mi][0], af[mi], &bf[0][0]);
                mma16(acc[mi][1], af[mi], &bf[0][2]);
                mma16(acc[mi][2], af[mi], &bf[1][0]);
                mma16(acc[mi][3], af[mi], &bf[1][2]);
            }
        }
    }

    #pragma unroll
    for (int mi = 0; mi < 4; mi++) {
        const int row = m0 + wm * 64 + mi * 16 + (lane >> 2);
        #pragma unroll
        for (int ni = 0; ni < 4; ni++) {
            const int col = n0 + wn * 32 + ni * 8 + (lane & 3) * 2;
            *(float2*)(g_logits + (size_t)row * EXPERTS + col)       = make_float2(acc[mi][ni][0], acc[mi][ni][1]);
            *(float2*)(g_logits + (size_t)(row + 8) * EXPERTS + col) = make_float2(acc[mi][ni][2], acc[mi][ni][3]);
        }
    }
}

// ---------------------------------------------------------------------------
// Topk: 2 tokens per warp, interleaved rounds (ILP hides redux latency).
// 4 warps/block -> 8 tokens/block; grid 1024.
// ---------------------------------------------------------------------------
__device__ __forceinline__ float sel_round(float b[24], float& vg_out) {
    float t12[12];
    #pragma unroll
    for (int j = 0; j < 12; j++) t12[j] = fmaxf(b[2 * j], b[2 * j + 1]);
    float t6[6];
    #pragma unroll
    for (int j = 0; j < 6; j++) t6[j] = fmaxf(t12[2 * j], t12[2 * j + 1]);
    vg_out = fmaxf(fmaxf(fmaxf(t6[0], t6[1]), fmaxf(t6[2], t6[3])), fmaxf(t6[4], t6[5]));
    return vg_out;
}

__global__ __launch_bounds__(128, 6)
void topk_warp2(const float* __restrict__ A, const float* __restrict__ W,
                const float* __restrict__ bias, float* __restrict__ out) {
    const int lane  = threadIdx.x & 31;
    const int wslot = threadIdx.x >> 5;            // 0..3
    const int t0 = blockIdx.x * 8 + wslot * 2;     // two consecutive tokens
    const int t1 = t0 + 1;

    __shared__ float s_cb[8][NCAND];
    __shared__ float s_cs[8][NCAND];
    __shared__ int   s_ce[8][NCAND];
    const int c0 = wslot * 2, c1 = c0 + 1;

    const float* r0 = g_logits + (size_t)t0 * EXPERTS;
    const float* r1 = g_logits + (size_t)t1 * EXPERTS;

    float b0[24], b1[24];
    #pragma unroll
    for (int j = 0; j < 24; j++) { b0[j] = r0[j * 32 + lane]; b1[j] = r1[j * 32 + lane]; }

    // softmax stats (interleaved)
    float m0 = b0[0], m1 = b1[0];
    #pragma unroll
    for (int j = 1; j < 24; j++) { m0 = fmaxf(m0, b0[j]); m1 = fmaxf(m1, b1[j]); }
    #pragma unroll
    for (int off = 16; off; off >>= 1) {
        m0 = fmaxf(m0, __shfl_xor_sync(0xffffffffu, m0, off));
        m1 = fmaxf(m1, __shfl_xor_sync(0xffffffffu, m1, off));
    }
    float s0 = 0.0f, s1 = 0.0f;
    #pragma unroll
    for (int j = 0; j < 24; j++) {
        b0[j] = expf(b0[j] - m0); s0 += b0[j];
        b1[j] = expf(b1[j] - m1); s1 += b1[j];
    }
    #pragma unroll
    for (int off = 16; off; off >>= 1) {
        s0 += __shfl_xor_sync(0xffffffffu, s0, off);
        s1 += __shfl_xor_sync(0xffffffffu, s1, off);
    }
    const float inv0 = 1.0f / s0, inv1 = 1.0f / s1;
    #pragma unroll
    for (int j = 0; j < 24; j++) {
        const float bj = __ldg(&bias[j * 32 + lane]);
        b0[j] = fmaf(b0[j], inv0, bj);
        b1[j] = fmaf(b1[j], inv1, bj);
    }

    // 13 interleaved selection rounds
    for (int sel = 0; sel < NCAND; sel++) {
        float v0, v1;
        sel_round(b0, v0);
        sel_round(b1, v1);

        const uint32_t gk0 = __reduce_max_sync(0xffffffffu, fkey(v0));
        const uint32_t gk1 = __reduce_max_sync(0xffffffffu, fkey(v1));
        const float vg0 = fval(gk0), vg1 = fval(gk1);

        uint32_t m0k = 0, m1k = 0;
        #pragma unroll
        for (int j = 0; j < 24; j++) {
            m0k |= (b0[j] == vg0) ? (1u << j) : 0u;
            m1k |= (b1[j] == vg1) ? (1u << j) : 0u;
        }
        const uint32_t c0d = m0k ? (uint32_t)((__ffs(m0k) - 1) * 32 + lane) : 0xFFFFFFFFu;
        const uint32_t c1d = m1k ? (uint32_t)((__ffs(m1k) - 1) * 32 + lane) : 0xFFFFFFFFu;
        const uint32_t i0 = __reduce_min_sync(0xffffffffu, c0d);
        const uint32_t i1 = __reduce_min_sync(0xffffffffu, c1d);

        if ((i0 & 31u) == (uint32_t)lane) {
            const int jw = i0 >> 5;
            #pragma unroll
            for (int j = 0; j < 24; j++) if (j == jw) b0[j] = -CUDART_INF_F;
        }
        if ((i1 & 31u) == (uint32_t)lane) {
            const int jw = i1 >> 5;
            #pragma unroll
            for (int j = 0; j < 24; j++) if (j == jw) b1[j] = -CUDART_INF_F;
        }
        if (lane == 0) {
            s_cb[c0][sel] = vg0; s_cs[c0][sel] = vg0 - __ldg(&bias[i0]); s_ce[c0][sel] = (int)i0;
            s_cb[c1][sel] = vg1; s_cs[c1][sel] = vg1 - __ldg(&bias[i1]); s_ce[c1][sel] = (int)i1;
        }
    }
    __syncwarp();

    // rescore + output per token (rare path; sequential over the 2 tokens)
    #pragma unroll
    for (int tt = 0; tt < 2; tt++) {
        const int tok = t0 + tt;
        const int cc  = c0 + tt;
        const float mm  = tt ? m1 : m0;
        const float inv = tt ? inv1 : inv0;

        unsigned fmask = 0;
        #pragma unroll
        for (int r = 0; r < NCAND - 1; r++)
            if (s_cb[cc][r] - s_cb[cc][r + 1] < TAU) fmask |= (3u << r);

        const float* x = A + (size_t)tok * HIDDEN;
        while (fmask) {
            const int r = __ffs(fmask) - 1;
            fmask &= fmask - 1;
            const int e = s_ce[cc][r];
            const float* w = W + (size_t)e * HIDDEN;
            float p = 0.0f;
            #pragma unroll 8
            for (int jj = lane; jj < HIDDEN; jj += 32)
                p = fmaf(x[jj], w[jj], p);
            #pragma unroll
            for (int off = 16; off; off >>= 1)
                p += __shfl_xor_sync(0xffffffffu, p, off);
            if (lane == 0) {
                const float sn = expf(p - mm) * inv;
                s_cs[cc][r] = sn;
                s_cb[cc][r] = sn + __ldg(&bias[e]);
            }
        }
        __syncwarp();

        if (lane < NCAND) {
            const float mv = s_cb[cc][lane];
            const int   me = s_ce[cc][lane];
            int rank = 0;
            #pragma unroll
            for (int j = 0; j < NCAND; j++) {
                const float jv = s_cb[cc][j];
                const int   je = s_ce[cc][j];
                if (jv > mv || (jv == mv && je < me)) rank++;
            }
            if (rank < TOPK) {
                out[(size_t)tok * TOPK + rank]                         = (float)me;
                out[(size_t)TOKENS * TOPK + (size_t)tok * TOPK + rank] = s_cs[cc][lane] * RSCALE;
            }
        }
        __syncwarp();
    }
}

extern "C" void kernel_launch(void* const* d_in, const int* in_sizes, int n_in,
                              void* d_out, int out_size) {
    const float* A    = (const float*)d_in[0];
    const float* W    = (const float*)d_in[1];
    const float* bias = (const float*)d_in[2];
    float* out = (float*)d_out;

    __half* dAh = nullptr; __half* dWh = nullptr;
    cudaGetSymbolAddress((void**)&dAh, g_Ah);
    cudaGetSymbolAddress((void**)&dWh, g_Wh);

    cvt_all_kernel<<<CVT_BLOCKS, 256>>>((const float4*)A, (const float4*)W,
                                        (uint2*)dAh, (uint2*)dWh);

    cudaFuncSetAttribute(router_gemm_cp, cudaFuncAttributeMaxDynamicSharedMemorySize, GEMM_SMEM);
    dim3 grid(EXPERTS / BN, TOKENS / BM);   // (6, 64)
    router_gemm_cp<<<grid, 256, GEMM_SMEM>>>();

    topk_warp2<<<TOKENS / 8, 128>>>(A, W, bias, out);
}